// round 12
// baseline (speedup 1.0000x reference)
#include <cuda_runtime.h>
#include <cstdint>

#define NB 8
#define RES 160
#define GCELLS (NB * RES * RES * RES)   // 32,768,000
#define NVEC   (GCELLS / 4)             // 8,192,000 float4 vectors
#define NWORDS (NVEC / 32)              // 256,000 bitmap words
#define EMA 0.95f
#define THRE 0.01f

// Scratch: per-cell max of (float bits of val) + 1. 0 == untouched sentinel.
// Zero-initialized at module load; sweep resets touched entries each replay.
__device__ unsigned int g_scratch[GCELLS];
// 1 bit per float4 vector of the grid: "this vector was touched this round".
__device__ unsigned int g_bitmap[NWORDS];

__device__ __forceinline__ int cell_coord(float p) {
    int g = (int)((p * 0.5f + 0.5f) * (float)RES);
    return min(max(g, 0), RES - 1);
}

__device__ __forceinline__ int lin_idx(int b, float x, float y, float z) {
    return ((b * RES + cell_coord(x)) * RES + cell_coord(y)) * RES + cell_coord(z);
}

__device__ __forceinline__ void scatter_one(int lin, float v) {
    atomicMax(&g_scratch[lin], __float_as_uint(v) + 1u);
    // mark the containing float4 vector as touched (bitmap is 1MB, L2-resident)
    atomicOr(&g_bitmap[lin >> 7], 1u << ((lin >> 2) & 31));
}

// 4 points per thread: 3x float4 pts + int4 bidx + float4 val, coalesced
// streaming loads, then fire-and-forget RED.MAX + RED.OR.
__global__ void scatter_max4_kernel(const float4* __restrict__ pts4,
                                    const int4* __restrict__ bidx4,
                                    const float4* __restrict__ val4,
                                    int n4) {
    int i = blockIdx.x * blockDim.x + threadIdx.x;
    if (i >= n4) return;

    float4 p0 = __ldcs(&pts4[3 * i + 0]);
    float4 p1 = __ldcs(&pts4[3 * i + 1]);
    float4 p2 = __ldcs(&pts4[3 * i + 2]);
    int4   b  = __ldcs(&bidx4[i]);
    float4 v  = __ldcs(&val4[i]);

    // pt0=(p0.x,p0.y,p0.z) pt1=(p0.w,p1.x,p1.y) pt2=(p1.z,p1.w,p2.x) pt3=(p2.y,p2.z,p2.w)
    scatter_one(lin_idx(b.x, p0.x, p0.y, p0.z), v.x);
    scatter_one(lin_idx(b.y, p0.w, p1.x, p1.y), v.y);
    scatter_one(lin_idx(b.z, p1.z, p1.w, p2.x), v.z);
    scatter_one(lin_idx(b.w, p2.y, p2.z, p2.w), v.w);
}

// scalar tail (n % 4 != 0; unused for n = 4194304)
__global__ void scatter_max_tail_kernel(const float* __restrict__ pts,
                                        const int* __restrict__ bidx,
                                        const float* __restrict__ val,
                                        int start, int n) {
    int i = start + blockIdx.x * blockDim.x + threadIdx.x;
    if (i >= n) return;
    int lin = lin_idx(bidx[i], pts[3 * i + 0], pts[3 * i + 1], pts[3 * i + 2]);
    scatter_one(lin, val[i]);
}

// 1 float4 per thread, bitmap-gated scratch access: untouched vectors never
// load scratch (skips the DRAM sector fetch entirely for ~36% of sectors).
__global__ void sweep_kernel(const float4* __restrict__ in,
                             float4* __restrict__ out_grid,
                             float4* __restrict__ out_occ,
                             int nvec, int write_occ) {
    int i = blockIdx.x * blockDim.x + threadIdx.x;
    if (i >= nvec) return;

    // threads i..i+31 of this warp share bitmap word i>>5 (broadcast load)
    unsigned int word = g_bitmap[i >> 5];
    bool touched = (word >> (i & 31)) & 1u;

    float4 g = __ldcs(&in[i]);
    float4 o = g;

    if (touched) {
        uint4 s = reinterpret_cast<const uint4*>(g_scratch)[i];
        o.x = s.x ? fmaxf(g.x * EMA, __uint_as_float(s.x - 1u)) : g.x;
        o.y = s.y ? fmaxf(g.y * EMA, __uint_as_float(s.y - 1u)) : g.y;
        o.z = s.z ? fmaxf(g.z * EMA, __uint_as_float(s.z - 1u)) : g.z;
        o.w = s.w ? fmaxf(g.w * EMA, __uint_as_float(s.w - 1u)) : g.w;
        // reset touched scratch for the next replay
        reinterpret_cast<uint4*>(g_scratch)[i] = make_uint4(0u, 0u, 0u, 0u);
    }

    __stcs(&out_grid[i], o);

    if (write_occ) {
        float4 q;
        q.x = (o.x > THRE) ? 1.0f : 0.0f;
        q.y = (o.y > THRE) ? 1.0f : 0.0f;
        q.z = (o.z > THRE) ? 1.0f : 0.0f;
        q.w = (o.w > THRE) ? 1.0f : 0.0f;
        __stcs(&out_occ[i], q);
    }

    // lane 0 resets the warp's bitmap word after all lanes consumed it
    __syncwarp();
    if ((i & 31) == 0 && word != 0u) {
        g_bitmap[i >> 5] = 0u;
    }
}

extern "C" void kernel_launch(void* const* d_in, const int* in_sizes, int n_in,
                              void* d_out, int out_size) {
    const float* grid_in = (const float*)d_in[0];   // occ_val_grid [8,160,160,160] f32
    const float* pts     = (const float*)d_in[1];   // [N,3] f32
    const int*   bidx    = (const int*)d_in[2];     // [N] i32
    const float* val     = (const float*)d_in[3];   // [N] f32

    int n = in_sizes[3];                 // N points
    float* out = (float*)d_out;

    int write_occ = (out_size >= 2 * GCELLS) ? 1 : 0;
    float4* out_grid = (float4*)out;
    float4* out_occ  = (float4*)(out + GCELLS);

    int n4 = n / 4;
    int rem = n - n4 * 4;
    if (n4 > 0) {
        int threads = 256;
        int blocks = (n4 + threads - 1) / threads;
        scatter_max4_kernel<<<blocks, threads>>>((const float4*)pts,
                                                 (const int4*)bidx,
                                                 (const float4*)val, n4);
    }
    if (rem > 0) {
        scatter_max_tail_kernel<<<1, 128>>>(pts, bidx, val, n4 * 4, n);
    }
    {
        int threads = 256;
        int blocks = (NVEC + threads - 1) / threads;
        sweep_kernel<<<blocks, threads>>>((const float4*)grid_in, out_grid,
                                          out_occ, NVEC, write_occ);
    }
}

// round 13
// speedup vs baseline: 1.9445x; 1.9445x over previous
#include <cuda_runtime.h>
#include <cstdint>

#define NB 8
#define RES 160
#define GCELLS (NB * RES * RES * RES)   // 32,768,000
#define EMA 0.95f
#define THRE 0.01f

// Scratch: per-cell max of (float bits of val) + 1. 0 == untouched sentinel.
// Zero-initialized at module load; sweep kernel resets touched entries so the
// state is identical at the start of every graph replay.
__device__ unsigned int g_scratch[GCELLS];

__device__ __forceinline__ int cell_coord(float p) {
    int g = (int)((p * 0.5f + 0.5f) * (float)RES);
    return min(max(g, 0), RES - 1);
}

__device__ __forceinline__ int lin_idx(int b, float x, float y, float z) {
    return ((b * RES + cell_coord(x)) * RES + cell_coord(y)) * RES + cell_coord(z);
}

// Single launch, two logical passes selected by blockIdx:
//   blocks [0, nb)     -> apply points with bidx in [0, NB/2)
//   blocks [nb, 2*nb)  -> apply points with bidx in [NB/2, NB)
// HW dispatches blocks roughly in order, so the low-half scratch (65.5 MB)
// is the atomic working set for the first phase and stays L2-resident, then
// the high half for the second phase — two-pass locality, zero extra launches.
// atomicMax is order-independent, so any wave overlap is still correct.
__global__ void scatter_max4_phased_kernel(const float4* __restrict__ pts4,
                                           const int4* __restrict__ bidx4,
                                           const float4* __restrict__ val4,
                                           int n4, int nb) {
    int blk = blockIdx.x;
    int b_lo, b_hi;
    if (blk < nb) { b_lo = 0; b_hi = NB / 2; }
    else          { b_lo = NB / 2; b_hi = NB; blk -= nb; }

    int i = blk * blockDim.x + threadIdx.x;
    if (i >= n4) return;

    float4 p0 = __ldcs(&pts4[3 * i + 0]);
    float4 p1 = __ldcs(&pts4[3 * i + 1]);
    float4 p2 = __ldcs(&pts4[3 * i + 2]);
    int4   b  = __ldcs(&bidx4[i]);
    float4 v  = __ldcs(&val4[i]);

    // pt0=(p0.x,p0.y,p0.z) pt1=(p0.w,p1.x,p1.y) pt2=(p1.z,p1.w,p2.x) pt3=(p2.y,p2.z,p2.w)
    if (b.x >= b_lo && b.x < b_hi) {
        int l = lin_idx(b.x, p0.x, p0.y, p0.z);
        atomicMax(&g_scratch[l], __float_as_uint(v.x) + 1u);
    }
    if (b.y >= b_lo && b.y < b_hi) {
        int l = lin_idx(b.y, p0.w, p1.x, p1.y);
        atomicMax(&g_scratch[l], __float_as_uint(v.y) + 1u);
    }
    if (b.z >= b_lo && b.z < b_hi) {
        int l = lin_idx(b.z, p1.z, p1.w, p2.x);
        atomicMax(&g_scratch[l], __float_as_uint(v.z) + 1u);
    }
    if (b.w >= b_lo && b.w < b_hi) {
        int l = lin_idx(b.w, p2.y, p2.z, p2.w);
        atomicMax(&g_scratch[l], __float_as_uint(v.w) + 1u);
    }
}

// scalar tail (n % 4 != 0; unused for n = 4194304)
__global__ void scatter_max_tail_kernel(const float* __restrict__ pts,
                                        const int* __restrict__ bidx,
                                        const float* __restrict__ val,
                                        int start, int n) {
    int i = start + blockIdx.x * blockDim.x + threadIdx.x;
    if (i >= n) return;
    int lin = lin_idx(bidx[i], pts[3 * i + 0], pts[3 * i + 1], pts[3 * i + 2]);
    atomicMax(&g_scratch[lin], __float_as_uint(val[i]) + 1u);
}

// 1 float4 per thread, fully coalesced, unconditional scratch load (max MLP).
__global__ void sweep_kernel(const float4* __restrict__ in,
                             float4* __restrict__ out_grid,
                             float4* __restrict__ out_occ,
                             int nvec, int write_occ) {
    int i = blockIdx.x * blockDim.x + threadIdx.x;
    if (i >= nvec) return;

    float4 g = __ldcs(&in[i]);
    uint4 s = reinterpret_cast<const uint4*>(g_scratch)[i];

    float4 o;
    o.x = s.x ? fmaxf(g.x * EMA, __uint_as_float(s.x - 1u)) : g.x;
    o.y = s.y ? fmaxf(g.y * EMA, __uint_as_float(s.y - 1u)) : g.y;
    o.z = s.z ? fmaxf(g.z * EMA, __uint_as_float(s.z - 1u)) : g.z;
    o.w = s.w ? fmaxf(g.w * EMA, __uint_as_float(s.w - 1u)) : g.w;

    __stcs(&out_grid[i], o);

    if (write_occ) {
        float4 q;
        q.x = (o.x > THRE) ? 1.0f : 0.0f;
        q.y = (o.y > THRE) ? 1.0f : 0.0f;
        q.z = (o.z > THRE) ? 1.0f : 0.0f;
        q.w = (o.w > THRE) ? 1.0f : 0.0f;
        __stcs(&out_occ[i], q);
    }

    // Reset only touched vectors so the next replay starts from zeros.
    if (s.x | s.y | s.z | s.w) {
        reinterpret_cast<uint4*>(g_scratch)[i] = make_uint4(0u, 0u, 0u, 0u);
    }
}

extern "C" void kernel_launch(void* const* d_in, const int* in_sizes, int n_in,
                              void* d_out, int out_size) {
    const float* grid_in = (const float*)d_in[0];   // occ_val_grid [8,160,160,160] f32
    const float* pts     = (const float*)d_in[1];   // [N,3] f32
    const int*   bidx    = (const int*)d_in[2];     // [N] i32
    const float* val     = (const float*)d_in[3];   // [N] f32

    int n = in_sizes[3];                 // N points
    float* out = (float*)d_out;

    int write_occ = (out_size >= 2 * GCELLS) ? 1 : 0;
    float4* out_grid = (float4*)out;
    float4* out_occ  = (float4*)(out + GCELLS);

    int n4 = n / 4;
    int rem = n - n4 * 4;
    if (n4 > 0) {
        int threads = 256;
        int nb = (n4 + threads - 1) / threads;
        scatter_max4_phased_kernel<<<2 * nb, threads>>>((const float4*)pts,
                                                        (const int4*)bidx,
                                                        (const float4*)val,
                                                        n4, nb);
    }
    if (rem > 0) {
        scatter_max_tail_kernel<<<1, 128>>>(pts, bidx, val, n4 * 4, n);
    }
    {
        int nvec = GCELLS / 4;           // 8,192,000
        int threads = 256;
        int blocks = (nvec + threads - 1) / threads;
        sweep_kernel<<<blocks, threads>>>((const float4*)grid_in, out_grid,
                                          out_occ, nvec, write_occ);
    }
}